// round 6
// baseline (speedup 1.0000x reference)
#include <cuda_runtime.h>
#include <cstdint>

#define N_FEAT 512
#define N_HID  16
#define N_CLS  40
#define MAX_NODES 100000
#define MAX_EDGES 3200000
#define SCAN_B    1024
#define MAX_NB    128   // ceil(100000/1024)=98

// ---------------------------------------------------------------------------
// Scratch (allocation-free: __device__ globals)
// ---------------------------------------------------------------------------
__device__ float  g_support1[MAX_NODES * N_HID];
__device__ float  g_h[MAX_NODES * N_HID];
__device__ float2 g_ebuf[MAX_EDGES];      // dst-bucketed (src_bits, w)
__device__ int    g_deg[MAX_NODES];
__device__ int    g_rowptr[MAX_NODES];
__device__ int    g_cursor[MAX_NODES];    // after scatter: == segment end
__device__ int    g_blksum[MAX_NB];

#define FMA_F32X2(d, a, b, c) \
    asm("fma.rn.f32x2 %0, %1, %2, %3;" : "=l"(d) : "l"(a), "l"(b), "l"(c))

// ---------------------------------------------------------------------------
// CSR build
// ---------------------------------------------------------------------------
__global__ void zero_deg_kernel(int n) {
    int i = blockIdx.x * blockDim.x + threadIdx.x;
    if (i < n) g_deg[i] = 0;
}

// histogram of dst, 4 edges/thread vectorized
__global__ __launch_bounds__(256) void hist_kernel(const int* __restrict__ dst, int nEdges) {
    int i = blockIdx.x * blockDim.x + threadIdx.x;
    int e = i * 4;
    if (e + 3 < nEdges) {
        int4 d4 = *reinterpret_cast<const int4*>(dst + e);
        atomicAdd(&g_deg[d4.x], 1);
        atomicAdd(&g_deg[d4.y], 1);
        atomicAdd(&g_deg[d4.z], 1);
        atomicAdd(&g_deg[d4.w], 1);
    } else {
        for (int j = e; j < nEdges; j++) atomicAdd(&g_deg[dst[j]], 1);
    }
}

__global__ __launch_bounds__(SCAN_B) void scanA_kernel(int n) {
    __shared__ int s[SCAN_B];
    int tid = threadIdx.x;
    int i = blockIdx.x * SCAN_B + tid;
    int v = (i < n) ? g_deg[i] : 0;
    s[tid] = v;
    __syncthreads();
    #pragma unroll
    for (int off = 1; off < SCAN_B; off <<= 1) {
        int t = (tid >= off) ? s[tid - off] : 0;
        __syncthreads();
        s[tid] += t;
        __syncthreads();
    }
    if (i < n) g_rowptr[i] = s[tid] - v;
    if (tid == SCAN_B - 1) g_blksum[blockIdx.x] = s[tid];
}

__global__ __launch_bounds__(MAX_NB) void scanB_kernel(int nb) {
    __shared__ int s[MAX_NB];
    int tid = threadIdx.x;
    int v = (tid < nb) ? g_blksum[tid] : 0;
    s[tid] = v;
    __syncthreads();
    #pragma unroll
    for (int off = 1; off < MAX_NB; off <<= 1) {
        int t = (tid >= off) ? s[tid - off] : 0;
        __syncthreads();
        s[tid] += t;
        __syncthreads();
    }
    if (tid < nb) g_blksum[tid] = s[tid] - v;
}

__global__ __launch_bounds__(256) void scanC_kernel(int n) {
    int i = blockIdx.x * blockDim.x + threadIdx.x;
    if (i >= n) return;
    int r = g_rowptr[i] + g_blksum[i >> 10];
    g_rowptr[i] = r;
    g_cursor[i] = r;
}

// scatter: 4 edges/thread, vectorized loads
__global__ __launch_bounds__(256) void scatter_kernel(
    const int* __restrict__ src, const int* __restrict__ dst,
    const float* __restrict__ ew, int nEdges)
{
    int i = blockIdx.x * blockDim.x + threadIdx.x;
    int e = i * 4;
    if (e + 3 < nEdges) {
        int4   s4 = *reinterpret_cast<const int4*>(src + e);
        int4   d4 = *reinterpret_cast<const int4*>(dst + e);
        float4 w4 = *reinterpret_cast<const float4*>(ew + e);
        int p0 = atomicAdd(&g_cursor[d4.x], 1);
        int p1 = atomicAdd(&g_cursor[d4.y], 1);
        int p2 = atomicAdd(&g_cursor[d4.z], 1);
        int p3 = atomicAdd(&g_cursor[d4.w], 1);
        g_ebuf[p0] = make_float2(__int_as_float(s4.x), w4.x);
        g_ebuf[p1] = make_float2(__int_as_float(s4.y), w4.y);
        g_ebuf[p2] = make_float2(__int_as_float(s4.z), w4.z);
        g_ebuf[p3] = make_float2(__int_as_float(s4.w), w4.w);
    } else {
        for (int j = e; j < nEdges; j++) {
            int pos = atomicAdd(&g_cursor[dst[j]], 1);
            g_ebuf[pos] = make_float2(__int_as_float(src[j]), ew[j]);
        }
    }
}

// ---------------------------------------------------------------------------
// gemm1: support1 = X @ W1  (R1's known-good version)
// ---------------------------------------------------------------------------
__global__ __launch_bounds__(256) void gemm1_kernel(
    const float* __restrict__ X, const float* __restrict__ W1, int nNodes)
{
    __shared__ __align__(16) float sW[N_FEAT * N_HID];  // 32 KB
    for (int i = threadIdx.x; i < N_FEAT * N_HID; i += blockDim.x)
        sW[i] = W1[i];
    __syncthreads();

    int row = blockIdx.x * blockDim.x + threadIdx.x;
    if (row >= nNodes) return;

    const float4* xr = reinterpret_cast<const float4*>(X + (size_t)row * N_FEAT);

    unsigned long long acc[8];
    #pragma unroll
    for (int p = 0; p < 8; p++) acc[p] = 0ULL;

    #pragma unroll 2
    for (int k4 = 0; k4 < N_FEAT / 4; k4++) {
        float4 xv = xr[k4];
        #pragma unroll
        for (int t = 0; t < 4; t++) {
            float xs = (t == 0) ? xv.x : (t == 1) ? xv.y : (t == 2) ? xv.z : xv.w;
            unsigned long long xx;
            asm("mov.b64 %0, {%1, %1};" : "=l"(xx) : "f"(xs));
            const float* wrow = sW + (k4 * 4 + t) * N_HID;
            #pragma unroll
            for (int q = 0; q < 2; q++) {
                ulonglong2 w0 = *reinterpret_cast<const ulonglong2*>(wrow + q * 8);
                FMA_F32X2(acc[q * 4 + 0], xx, w0.x, acc[q * 4 + 0]);
                FMA_F32X2(acc[q * 4 + 1], xx, w0.y, acc[q * 4 + 1]);
                ulonglong2 w1 = *reinterpret_cast<const ulonglong2*>(wrow + q * 8 + 4);
                FMA_F32X2(acc[q * 4 + 2], xx, w1.x, acc[q * 4 + 2]);
                FMA_F32X2(acc[q * 4 + 3], xx, w1.y, acc[q * 4 + 3]);
            }
        }
    }

    float* o = g_support1 + (size_t)row * N_HID;
    #pragma unroll
    for (int q = 0; q < 4; q++) {
        ulonglong2 st;
        st.x = acc[q * 2 + 0];
        st.y = acc[q * 2 + 1];
        *reinterpret_cast<ulonglong2*>(o + q * 4) = st;
    }
}

// ---------------------------------------------------------------------------
// Warp-per-node gather, unrolled x2. Lanes in groups of 4 per edge,
// 8 (16 unrolled) edges/iter, butterfly-reduce across groups.
// ---------------------------------------------------------------------------
__device__ __forceinline__ float4 warp_gather(
    int node, int lane, const float* __restrict__ feat)
{
    int beg = g_rowptr[node];
    int end = g_cursor[node];       // scatter left cursor == segment end
    int grp = lane >> 2;            // 0..7
    int c   = (lane & 3) << 2;      // 0,4,8,12

    float4 acc = make_float4(0.f, 0.f, 0.f, 0.f);

    int e = beg + grp;
    for (; e + 8 < end; e += 16) {
        float2 ea = __ldg(g_ebuf + e);
        float2 eb = __ldg(g_ebuf + e + 8);
        int   sa = __float_as_int(ea.x);
        int   sb = __float_as_int(eb.x);
        float4 va = *reinterpret_cast<const float4*>(feat + (size_t)sa * N_HID + c);
        float4 vb = *reinterpret_cast<const float4*>(feat + (size_t)sb * N_HID + c);
        acc.x = fmaf(va.x, ea.y, acc.x);
        acc.y = fmaf(va.y, ea.y, acc.y);
        acc.z = fmaf(va.z, ea.y, acc.z);
        acc.w = fmaf(va.w, ea.y, acc.w);
        acc.x = fmaf(vb.x, eb.y, acc.x);
        acc.y = fmaf(vb.y, eb.y, acc.y);
        acc.z = fmaf(vb.z, eb.y, acc.z);
        acc.w = fmaf(vb.w, eb.y, acc.w);
    }
    for (; e < end; e += 8) {
        float2 ew2 = __ldg(g_ebuf + e);
        int   s = __float_as_int(ew2.x);
        float w = ew2.y;
        float4 v = *reinterpret_cast<const float4*>(feat + (size_t)s * N_HID + c);
        acc.x = fmaf(v.x, w, acc.x);
        acc.y = fmaf(v.y, w, acc.y);
        acc.z = fmaf(v.z, w, acc.z);
        acc.w = fmaf(v.w, w, acc.w);
    }

    #pragma unroll
    for (int off = 16; off >= 4; off >>= 1) {
        acc.x += __shfl_xor_sync(0xffffffffu, acc.x, off);
        acc.y += __shfl_xor_sync(0xffffffffu, acc.y, off);
        acc.z += __shfl_xor_sync(0xffffffffu, acc.z, off);
        acc.w += __shfl_xor_sync(0xffffffffu, acc.w, off);
    }
    return acc;
}

// conv1: h = relu(gather(support1) + b1)
__global__ __launch_bounds__(256) void gconv1_kernel(
    const float* __restrict__ b1, int nNodes)
{
    int lane = threadIdx.x & 31;
    int node = blockIdx.x * 8 + (threadIdx.x >> 5);
    if (node >= nNodes) return;

    float4 acc = warp_gather(node, lane, g_support1);

    if (lane < 4) {
        float4 b = *reinterpret_cast<const float4*>(b1 + lane * 4);
        acc.x = fmaxf(acc.x + b.x, 0.f);
        acc.y = fmaxf(acc.y + b.y, 0.f);
        acc.z = fmaxf(acc.z + b.z, 0.f);
        acc.w = fmaxf(acc.w + b.w, 0.f);
        *reinterpret_cast<float4*>(g_h + (size_t)node * N_HID + lane * 4) = acc;
    }
}

// conv2 + head: out = log_softmax(gather(h) @ W2 + b2)
__global__ __launch_bounds__(256) void gconv2_head_kernel(
    const float* __restrict__ W2, const float* __restrict__ b2,
    float* __restrict__ out, int nNodes)
{
    __shared__ float sW[N_HID * N_CLS];
    __shared__ float sb[N_CLS];
    __shared__ float sv[8][N_HID];
    for (int i = threadIdx.x; i < N_HID * N_CLS; i += blockDim.x) sW[i] = W2[i];
    for (int i = threadIdx.x; i < N_CLS; i += blockDim.x) sb[i] = b2[i];
    __syncthreads();

    int lane = threadIdx.x & 31;
    int wrp  = threadIdx.x >> 5;
    int node = blockIdx.x * 8 + wrp;
    if (node >= nNodes) return;

    float4 acc = warp_gather(node, lane, g_h);

    if (lane < 4)
        *reinterpret_cast<float4*>(&sv[wrp][lane * 4]) = acc;
    __syncwarp();

    int c1 = 32 + (lane & 7);
    float y0 = sb[lane];
    float y1 = sb[c1];
    #pragma unroll
    for (int k = 0; k < N_HID; k++) {
        float vk = sv[wrp][k];
        y0 = fmaf(vk, sW[k * N_CLS + lane], y0);
        y1 = fmaf(vk, sW[k * N_CLS + c1], y1);
    }
    bool has1 = (lane < 8);

    float m = has1 ? fmaxf(y0, y1) : y0;
    #pragma unroll
    for (int off = 16; off >= 1; off >>= 1)
        m = fmaxf(m, __shfl_xor_sync(0xffffffffu, m, off));

    float ssum = __expf(y0 - m) + (has1 ? __expf(y1 - m) : 0.f);
    #pragma unroll
    for (int off = 16; off >= 1; off >>= 1)
        ssum += __shfl_xor_sync(0xffffffffu, ssum, off);

    float lse = m + __logf(ssum);

    float* o = out + (size_t)node * N_CLS;
    o[lane] = y0 - lse;
    if (has1) o[c1] = y1 - lse;
}

// ---------------------------------------------------------------------------
// Launcher — build chain forked onto a second stream, overlapping gemm1.
// ---------------------------------------------------------------------------
extern "C" void kernel_launch(void* const* d_in, const int* in_sizes, int n_in,
                              void* d_out, int out_size)
{
    const float* x        = (const float*)d_in[0];
    const int*   edge_src = (const int*)  d_in[1];
    const int*   edge_dst = (const int*)  d_in[2];
    const float* edge_w   = (const float*)d_in[3];
    const float* W1       = (const float*)d_in[4];
    const float* b1       = (const float*)d_in[5];
    const float* W2       = (const float*)d_in[6];
    const float* b2       = (const float*)d_in[7];
    float* out = (float*)d_out;

    int nNodes = in_sizes[0] / N_FEAT;
    int nEdges = in_sizes[1];
    int nb = (nNodes + SCAN_B - 1) / SCAN_B;
    int e4blocks = ((nEdges + 3) / 4 + 255) / 256;

    // Fork: build chain on s2, gemm1 on default stream, join before gathers.
    cudaStream_t s2 = 0;
    cudaEvent_t evF = 0, evJ = 0;
    bool forked =
        (cudaStreamCreateWithFlags(&s2, cudaStreamNonBlocking) == cudaSuccess) &&
        (cudaEventCreateWithFlags(&evF, cudaEventDisableTiming) == cudaSuccess) &&
        (cudaEventCreateWithFlags(&evJ, cudaEventDisableTiming) == cudaSuccess);
    if (!forked) s2 = 0;

    if (forked) {
        cudaEventRecord(evF, 0);
        cudaStreamWaitEvent(s2, evF, 0);
    }

    // --- build chain (stream s2) ---
    zero_deg_kernel<<<(nNodes + 255) / 256, 256, 0, s2>>>(nNodes);
    hist_kernel<<<e4blocks, 256, 0, s2>>>(edge_dst, nEdges);
    scanA_kernel<<<nb, SCAN_B, 0, s2>>>(nNodes);
    scanB_kernel<<<1, MAX_NB, 0, s2>>>(nb);
    scanC_kernel<<<(nNodes + 255) / 256, 256, 0, s2>>>(nNodes);
    scatter_kernel<<<e4blocks, 256, 0, s2>>>(edge_src, edge_dst, edge_w, nEdges);

    // --- dense projection (default stream, concurrent with build) ---
    gemm1_kernel<<<(nNodes + 255) / 256, 256>>>(x, W1, nNodes);

    if (forked) {
        cudaEventRecord(evJ, s2);
        cudaStreamWaitEvent(0, evJ, 0);
    }

    // --- gathers (default stream) ---
    int gblocks = (nNodes + 7) / 8;
    gconv1_kernel<<<gblocks, 256>>>(b1, nNodes);
    gconv2_head_kernel<<<gblocks, 256>>>(W2, b2, out, nNodes);
}

// round 7
// speedup vs baseline: 1.2946x; 1.2946x over previous
#include <cuda_runtime.h>
#include <cstdint>

#define N_FEAT 512
#define N_HID  16
#define N_CLS  40
#define MAX_NODES 100000

// Scratch (allocation-free: __device__ globals)
__device__ float g_support1[MAX_NODES * N_HID];  // X @ W1
__device__ float g_agg1[MAX_NODES * N_HID];      // segment_sum conv1
__device__ float g_h[MAX_NODES * N_HID];         // relu(agg1 + b1)
__device__ float g_agg2[MAX_NODES * N_HID];      // segment_sum of h (16-dim)

#define FMA_F32X2(d, a, b, c) \
    asm("fma.rn.f32x2 %0, %1, %2, %3;" : "=l"(d) : "l"(a), "l"(b), "l"(c))

// ---------------------------------------------------------------------------
// Kernel 0: zero both aggregation buffers
// ---------------------------------------------------------------------------
__global__ void zero_kernel(int n_float4) {
    int i = blockIdx.x * blockDim.x + threadIdx.x;
    if (i >= n_float4) return;
    float4 z = make_float4(0.f, 0.f, 0.f, 0.f);
    reinterpret_cast<float4*>(g_agg1)[i] = z;
    reinterpret_cast<float4*>(g_agg2)[i] = z;
}

// ---------------------------------------------------------------------------
// Kernel 1: support1 = X @ W1   [nNodes,512] @ [512,16]
// 256 thr/block, 2 rows/thread (t, t+256) = 512 rows/block.
// X staged coalesced through padded smem tile (K-chunks of 16);
// W chunk staged in SMEM (1 KB) — LDS broadcasts, no LDG floor.
// FMA-bound: ~31us floor.
// ---------------------------------------------------------------------------
#define GKC   16
#define GROWS 512
#define GPAD  17

__global__ __launch_bounds__(256) void gemm1_kernel(
    const float* __restrict__ X, const float* __restrict__ W1, int nNodes)
{
    __shared__ float tile[GROWS * GPAD];              // 34816 B
    __shared__ __align__(16) float sWc[GKC * N_HID];  // 1 KB

    int t = threadIdx.x;
    int rowbase = blockIdx.x * GROWS;

    unsigned long long accA[8], accB[8];
    #pragma unroll
    for (int p = 0; p < 8; p++) { accA[p] = 0ULL; accB[p] = 0ULL; }

    for (int kc = 0; kc < N_FEAT; kc += GKC) {
        // W chunk: rows kc..kc+15 are contiguous (row-major [512][16])
        sWc[t] = W1[kc * N_HID + t];

        // stage 512 rows x 16 floats: 2048 float4, 8/thread, coalesced-ish
        #pragma unroll
        for (int j = 0; j < 8; j++) {
            int idx = t + 256 * j;
            int row = idx >> 2;        // 0..511
            int c4  = idx & 3;         // 0..3
            int grow = rowbase + row;
            float4 v = make_float4(0.f, 0.f, 0.f, 0.f);
            if (grow < nNodes)
                v = *reinterpret_cast<const float4*>(
                        X + (size_t)grow * N_FEAT + kc + c4 * 4);
            float* tp = tile + row * GPAD + c4 * 4;
            tp[0] = v.x; tp[1] = v.y; tp[2] = v.z; tp[3] = v.w;
        }
        __syncthreads();

        const float* tA = tile + t * GPAD;
        const float* tB = tile + (t + 256) * GPAD;

        #pragma unroll
        for (int kk = 0; kk < GKC; kk++) {
            float xa = tA[kk];
            float xb = tB[kk];
            unsigned long long xxa, xxb;
            asm("mov.b64 %0, {%1, %1};" : "=l"(xxa) : "f"(xa));
            asm("mov.b64 %0, {%1, %1};" : "=l"(xxb) : "f"(xb));

            const ulonglong2* wr =
                reinterpret_cast<const ulonglong2*>(sWc + kk * N_HID);
            ulonglong2 w0 = wr[0];   // LDS.128 broadcast
            ulonglong2 w1 = wr[1];
            ulonglong2 w2 = wr[2];
            ulonglong2 w3 = wr[3];

            FMA_F32X2(accA[0], xxa, w0.x, accA[0]);
            FMA_F32X2(accA[1], xxa, w0.y, accA[1]);
            FMA_F32X2(accA[2], xxa, w1.x, accA[2]);
            FMA_F32X2(accA[3], xxa, w1.y, accA[3]);
            FMA_F32X2(accA[4], xxa, w2.x, accA[4]);
            FMA_F32X2(accA[5], xxa, w2.y, accA[5]);
            FMA_F32X2(accA[6], xxa, w3.x, accA[6]);
            FMA_F32X2(accA[7], xxa, w3.y, accA[7]);

            FMA_F32X2(accB[0], xxb, w0.x, accB[0]);
            FMA_F32X2(accB[1], xxb, w0.y, accB[1]);
            FMA_F32X2(accB[2], xxb, w1.x, accB[2]);
            FMA_F32X2(accB[3], xxb, w1.y, accB[3]);
            FMA_F32X2(accB[4], xxb, w2.x, accB[4]);
            FMA_F32X2(accB[5], xxb, w2.y, accB[5]);
            FMA_F32X2(accB[6], xxb, w3.x, accB[6]);
            FMA_F32X2(accB[7], xxb, w3.y, accB[7]);
        }
        __syncthreads();
    }

    int r0 = rowbase + t;
    int r1 = rowbase + t + 256;
    if (r0 < nNodes) {
        float* o = g_support1 + (size_t)r0 * N_HID;
        #pragma unroll
        for (int q = 0; q < 4; q++) {
            ulonglong2 st; st.x = accA[q * 2]; st.y = accA[q * 2 + 1];
            *reinterpret_cast<ulonglong2*>(o + q * 4) = st;
        }
    }
    if (r1 < nNodes) {
        float* o = g_support1 + (size_t)r1 * N_HID;
        #pragma unroll
        for (int q = 0; q < 4; q++) {
            ulonglong2 st; st.x = accB[q * 2]; st.y = accB[q * 2 + 1];
            *reinterpret_cast<ulonglong2*>(o + q * 4) = st;
        }
    }
}

// ---------------------------------------------------------------------------
// Kernel 2: edge aggregation (R1 verbatim: 4 lanes/edge, red.global.add.v4)
// ---------------------------------------------------------------------------
__global__ __launch_bounds__(256) void aggregate_kernel(
    const int* __restrict__ src, const int* __restrict__ dst,
    const float* __restrict__ ew, const float* __restrict__ feat,
    float* __restrict__ out, int nEdges)
{
    int gid = blockIdx.x * blockDim.x + threadIdx.x;
    int e = gid >> 2;
    if (e >= nEdges) return;
    int c = (gid & 3) << 2;

    int s = __ldg(src + e);
    int d = __ldg(dst + e);
    float w = __ldg(ew + e);

    float4 v = *reinterpret_cast<const float4*>(feat + (size_t)s * N_HID + c);
    float* o = out + (size_t)d * N_HID + c;
    asm volatile("red.global.add.v4.f32 [%0], {%1, %2, %3, %4};"
                 :: "l"(o), "f"(v.x * w), "f"(v.y * w), "f"(v.z * w), "f"(v.w * w)
                 : "memory");
}

// ---------------------------------------------------------------------------
// Kernel 3: h = relu(agg1 + b1)
// ---------------------------------------------------------------------------
__global__ __launch_bounds__(256) void relu_bias_kernel(
    const float* __restrict__ b1, int n_float4)
{
    int i = blockIdx.x * blockDim.x + threadIdx.x;
    if (i >= n_float4) return;
    int j = (i & 3) << 2;
    float4 v = reinterpret_cast<const float4*>(g_agg1)[i];
    float4 b = *reinterpret_cast<const float4*>(b1 + j);
    v.x = fmaxf(v.x + b.x, 0.f);
    v.y = fmaxf(v.y + b.y, 0.f);
    v.z = fmaxf(v.z + b.z, 0.f);
    v.w = fmaxf(v.w + b.w, 0.f);
    reinterpret_cast<float4*>(g_h)[i] = v;
}

// ---------------------------------------------------------------------------
// Kernel 4: out = log_softmax(agg2 @ W2 + b2)
// ---------------------------------------------------------------------------
__global__ __launch_bounds__(128) void head_kernel(
    const float* __restrict__ W2, const float* __restrict__ b2,
    float* __restrict__ out, int nNodes)
{
    __shared__ float sW[N_HID * N_CLS];
    __shared__ float sb[N_CLS];
    for (int i = threadIdx.x; i < N_HID * N_CLS; i += blockDim.x) sW[i] = W2[i];
    for (int i = threadIdx.x; i < N_CLS; i += blockDim.x) sb[i] = b2[i];
    __syncthreads();

    int node = blockIdx.x * blockDim.x + threadIdx.x;
    if (node >= nNodes) return;

    float v[N_HID];
    const float4* vp = reinterpret_cast<const float4*>(g_agg2 + (size_t)node * N_HID);
    #pragma unroll
    for (int q = 0; q < 4; q++) {
        float4 tt = vp[q];
        v[q * 4 + 0] = tt.x; v[q * 4 + 1] = tt.y; v[q * 4 + 2] = tt.z; v[q * 4 + 3] = tt.w;
    }

    float y[N_CLS];
    #pragma unroll
    for (int c = 0; c < N_CLS; c++) y[c] = sb[c];
    #pragma unroll
    for (int k = 0; k < N_HID; k++) {
        float vk = v[k];
        const float* wr = sW + k * N_CLS;
        #pragma unroll
        for (int c = 0; c < N_CLS; c++)
            y[c] = fmaf(vk, wr[c], y[c]);
    }

    float mx = y[0];
    #pragma unroll
    for (int c = 1; c < N_CLS; c++) mx = fmaxf(mx, y[c]);
    float sum = 0.f;
    #pragma unroll
    for (int c = 0; c < N_CLS; c++) sum += __expf(y[c] - mx);
    float lse = mx + __logf(sum);

    float* o = out + (size_t)node * N_CLS;
    #pragma unroll
    for (int q = 0; q < N_CLS / 4; q++) {
        float4 st = make_float4(y[q * 4 + 0] - lse, y[q * 4 + 1] - lse,
                                y[q * 4 + 2] - lse, y[q * 4 + 3] - lse);
        *reinterpret_cast<float4*>(o + q * 4) = st;
    }
}

// ---------------------------------------------------------------------------
// Launcher (R1 structure)
// ---------------------------------------------------------------------------
extern "C" void kernel_launch(void* const* d_in, const int* in_sizes, int n_in,
                              void* d_out, int out_size)
{
    const float* x        = (const float*)d_in[0];
    const int*   edge_src = (const int*)  d_in[1];
    const int*   edge_dst = (const int*)  d_in[2];
    const float* edge_w   = (const float*)d_in[3];
    const float* W1       = (const float*)d_in[4];
    const float* b1       = (const float*)d_in[5];
    const float* W2       = (const float*)d_in[6];
    const float* b2       = (const float*)d_in[7];
    float* out = (float*)d_out;

    int nNodes = in_sizes[0] / N_FEAT;
    int nEdges = in_sizes[1];

    float* d_support1; cudaGetSymbolAddress((void**)&d_support1, g_support1);
    float* d_agg1;     cudaGetSymbolAddress((void**)&d_agg1, g_agg1);
    float* d_h;        cudaGetSymbolAddress((void**)&d_h, g_h);
    float* d_agg2;     cudaGetSymbolAddress((void**)&d_agg2, g_agg2);

    int n_f4 = nNodes * N_HID / 4;

    zero_kernel<<<(n_f4 + 255) / 256, 256>>>(n_f4);

    gemm1_kernel<<<(nNodes + GROWS - 1) / GROWS, 256>>>(x, W1, nNodes);

    int aggThreads = nEdges * 4;
    aggregate_kernel<<<(aggThreads + 255) / 256, 256>>>(
        edge_src, edge_dst, edge_w, d_support1, d_agg1, nEdges);

    relu_bias_kernel<<<(n_f4 + 255) / 256, 256>>>(b1, n_f4);

    aggregate_kernel<<<(aggThreads + 255) / 256, 256>>>(
        edge_src, edge_dst, edge_w, d_h, d_agg2, nEdges);

    head_kernel<<<(nNodes + 127) / 128, 128>>>(W2, b2, out, nNodes);
}

// round 8
// speedup vs baseline: 1.3869x; 1.0713x over previous
#include <cuda_runtime.h>
#include <cstdint>

#define N_FEAT 512
#define N_HID  16
#define N_CLS  40
#define MAX_NODES 100000

// Scratch (allocation-free: __device__ globals)
__device__ float g_support1[MAX_NODES * N_HID];  // X @ W1
__device__ float g_agg1[MAX_NODES * N_HID];      // segment_sum conv1
__device__ float g_agg2[MAX_NODES * N_HID];      // segment_sum conv2 (16-dim)

#define FMA_F32X2(d, a, b, c) \
    asm("fma.rn.f32x2 %0, %1, %2, %3;" : "=l"(d) : "l"(a), "l"(b), "l"(c))

// ---------------------------------------------------------------------------
// Kernel 0: zero both aggregation buffers
// ---------------------------------------------------------------------------
__global__ void zero_kernel(int n_float4) {
    int i = blockIdx.x * blockDim.x + threadIdx.x;
    if (i >= n_float4) return;
    float4 z = make_float4(0.f, 0.f, 0.f, 0.f);
    reinterpret_cast<float4*>(g_agg1)[i] = z;
    reinterpret_cast<float4*>(g_agg2)[i] = z;
}

// ---------------------------------------------------------------------------
// Kernel 1: support1 = X @ W1   [nNodes,512] @ [512,16]
// 128 thr/block, 2 rows/thread = 256 rows/block (391 blocks -> good wave
// balance). X staged coalesced via padded smem tile; W chunk in SMEM.
// ---------------------------------------------------------------------------
#define GKC   16
#define GROWS 256
#define GPAD  17

__global__ __launch_bounds__(128) void gemm1_kernel(
    const float* __restrict__ X, const float* __restrict__ W1, int nNodes)
{
    __shared__ float tile[GROWS * GPAD];              // 17408 B
    __shared__ __align__(16) float sWc[GKC * N_HID];  // 1 KB

    int t = threadIdx.x;
    int rowbase = blockIdx.x * GROWS;

    unsigned long long accA[8], accB[8];
    #pragma unroll
    for (int p = 0; p < 8; p++) { accA[p] = 0ULL; accB[p] = 0ULL; }

    for (int kc = 0; kc < N_FEAT; kc += GKC) {
        // W chunk: rows kc..kc+15 contiguous (row-major [512][16]) = 256 floats
        sWc[t]       = W1[kc * N_HID + t];
        sWc[t + 128] = W1[kc * N_HID + t + 128];

        // stage 256 rows x 16 floats: 1024 float4, 8 per thread, coalesced
        #pragma unroll
        for (int j = 0; j < 8; j++) {
            int idx = t + 128 * j;
            int row = idx >> 2;        // 0..255
            int c4  = idx & 3;         // 0..3
            int grow = rowbase + row;
            float4 v = make_float4(0.f, 0.f, 0.f, 0.f);
            if (grow < nNodes)
                v = *reinterpret_cast<const float4*>(
                        X + (size_t)grow * N_FEAT + kc + c4 * 4);
            float* tp = tile + row * GPAD + c4 * 4;
            tp[0] = v.x; tp[1] = v.y; tp[2] = v.z; tp[3] = v.w;
        }
        __syncthreads();

        const float* tA = tile + t * GPAD;
        const float* tB = tile + (t + 128) * GPAD;

        #pragma unroll
        for (int kk = 0; kk < GKC; kk++) {
            float xa = tA[kk];
            float xb = tB[kk];
            unsigned long long xxa, xxb;
            asm("mov.b64 %0, {%1, %1};" : "=l"(xxa) : "f"(xa));
            asm("mov.b64 %0, {%1, %1};" : "=l"(xxb) : "f"(xb));

            const ulonglong2* wr =
                reinterpret_cast<const ulonglong2*>(sWc + kk * N_HID);
            ulonglong2 w0 = wr[0];   // LDS.128 broadcast
            ulonglong2 w1 = wr[1];
            ulonglong2 w2 = wr[2];
            ulonglong2 w3 = wr[3];

            FMA_F32X2(accA[0], xxa, w0.x, accA[0]);
            FMA_F32X2(accA[1], xxa, w0.y, accA[1]);
            FMA_F32X2(accA[2], xxa, w1.x, accA[2]);
            FMA_F32X2(accA[3], xxa, w1.y, accA[3]);
            FMA_F32X2(accA[4], xxa, w2.x, accA[4]);
            FMA_F32X2(accA[5], xxa, w2.y, accA[5]);
            FMA_F32X2(accA[6], xxa, w3.x, accA[6]);
            FMA_F32X2(accA[7], xxa, w3.y, accA[7]);

            FMA_F32X2(accB[0], xxb, w0.x, accB[0]);
            FMA_F32X2(accB[1], xxb, w0.y, accB[1]);
            FMA_F32X2(accB[2], xxb, w1.x, accB[2]);
            FMA_F32X2(accB[3], xxb, w1.y, accB[3]);
            FMA_F32X2(accB[4], xxb, w2.x, accB[4]);
            FMA_F32X2(accB[5], xxb, w2.y, accB[5]);
            FMA_F32X2(accB[6], xxb, w3.x, accB[6]);
            FMA_F32X2(accB[7], xxb, w3.y, accB[7]);
        }
        __syncthreads();
    }

    int r0 = rowbase + t;
    int r1 = rowbase + t + 128;
    if (r0 < nNodes) {
        float* o = g_support1 + (size_t)r0 * N_HID;
        #pragma unroll
        for (int q = 0; q < 4; q++) {
            ulonglong2 st; st.x = accA[q * 2]; st.y = accA[q * 2 + 1];
            *reinterpret_cast<ulonglong2*>(o + q * 4) = st;
        }
    }
    if (r1 < nNodes) {
        float* o = g_support1 + (size_t)r1 * N_HID;
        #pragma unroll
        for (int q = 0; q < 4; q++) {
            ulonglong2 st; st.x = accB[q * 2]; st.y = accB[q * 2 + 1];
            *reinterpret_cast<ulonglong2*>(o + q * 4) = st;
        }
    }
}

// ---------------------------------------------------------------------------
// Kernel 2a: conv1 aggregation (4 lanes/edge, red.global.add.v4)
// ---------------------------------------------------------------------------
__global__ __launch_bounds__(256) void aggregate1_kernel(
    const int* __restrict__ src, const int* __restrict__ dst,
    const float* __restrict__ ew, int nEdges)
{
    int gid = blockIdx.x * blockDim.x + threadIdx.x;
    int e = gid >> 2;
    if (e >= nEdges) return;
    int c = (gid & 3) << 2;

    int s = __ldg(src + e);
    int d = __ldg(dst + e);
    float w = __ldg(ew + e);

    float4 v = *reinterpret_cast<const float4*>(g_support1 + (size_t)s * N_HID + c);
    float* o = g_agg1 + (size_t)d * N_HID + c;
    asm volatile("red.global.add.v4.f32 [%0], {%1, %2, %3, %4};"
                 :: "l"(o), "f"(v.x * w), "f"(v.y * w), "f"(v.z * w), "f"(v.w * w)
                 : "memory");
}

// ---------------------------------------------------------------------------
// Kernel 2b: conv2 aggregation with FUSED bias+relu on the gathered value:
//   agg2[d] += w * relu(agg1[s] + b1)       (h never materialized)
// ---------------------------------------------------------------------------
__global__ __launch_bounds__(256) void aggregate2_kernel(
    const int* __restrict__ src, const int* __restrict__ dst,
    const float* __restrict__ ew, const float* __restrict__ b1, int nEdges)
{
    int gid = blockIdx.x * blockDim.x + threadIdx.x;
    int e = gid >> 2;
    if (e >= nEdges) return;
    int c = (gid & 3) << 2;

    int s = __ldg(src + e);
    int d = __ldg(dst + e);
    float w = __ldg(ew + e);

    float4 v = *reinterpret_cast<const float4*>(g_agg1 + (size_t)s * N_HID + c);
    float4 b = *reinterpret_cast<const float4*>(b1 + c);   // L1-hot broadcast
    v.x = fmaxf(v.x + b.x, 0.f) * w;
    v.y = fmaxf(v.y + b.y, 0.f) * w;
    v.z = fmaxf(v.z + b.z, 0.f) * w;
    v.w = fmaxf(v.w + b.w, 0.f) * w;

    float* o = g_agg2 + (size_t)d * N_HID + c;
    asm volatile("red.global.add.v4.f32 [%0], {%1, %2, %3, %4};"
                 :: "l"(o), "f"(v.x), "f"(v.y), "f"(v.z), "f"(v.w)
                 : "memory");
}

// ---------------------------------------------------------------------------
// Kernel 3: out = log_softmax(agg2 @ W2 + b2)
// ---------------------------------------------------------------------------
__global__ __launch_bounds__(128) void head_kernel(
    const float* __restrict__ W2, const float* __restrict__ b2,
    float* __restrict__ out, int nNodes)
{
    __shared__ float sW[N_HID * N_CLS];
    __shared__ float sb[N_CLS];
    for (int i = threadIdx.x; i < N_HID * N_CLS; i += blockDim.x) sW[i] = W2[i];
    for (int i = threadIdx.x; i < N_CLS; i += blockDim.x) sb[i] = b2[i];
    __syncthreads();

    int node = blockIdx.x * blockDim.x + threadIdx.x;
    if (node >= nNodes) return;

    float v[N_HID];
    const float4* vp = reinterpret_cast<const float4*>(g_agg2 + (size_t)node * N_HID);
    #pragma unroll
    for (int q = 0; q < 4; q++) {
        float4 tt = vp[q];
        v[q * 4 + 0] = tt.x; v[q * 4 + 1] = tt.y; v[q * 4 + 2] = tt.z; v[q * 4 + 3] = tt.w;
    }

    float y[N_CLS];
    #pragma unroll
    for (int c = 0; c < N_CLS; c++) y[c] = sb[c];
    #pragma unroll
    for (int k = 0; k < N_HID; k++) {
        float vk = v[k];
        const float* wr = sW + k * N_CLS;
        #pragma unroll
        for (int c = 0; c < N_CLS; c++)
            y[c] = fmaf(vk, wr[c], y[c]);
    }

    float mx = y[0];
    #pragma unroll
    for (int c = 1; c < N_CLS; c++) mx = fmaxf(mx, y[c]);
    float sum = 0.f;
    #pragma unroll
    for (int c = 0; c < N_CLS; c++) sum += __expf(y[c] - mx);
    float lse = mx + __logf(sum);

    float* o = out + (size_t)node * N_CLS;
    #pragma unroll
    for (int q = 0; q < N_CLS / 4; q++) {
        float4 st = make_float4(y[q * 4 + 0] - lse, y[q * 4 + 1] - lse,
                                y[q * 4 + 2] - lse, y[q * 4 + 3] - lse);
        *reinterpret_cast<float4*>(o + q * 4) = st;
    }
}

// ---------------------------------------------------------------------------
// Launcher — zero forked onto a side stream, overlapping gemm1.
// ---------------------------------------------------------------------------
extern "C" void kernel_launch(void* const* d_in, const int* in_sizes, int n_in,
                              void* d_out, int out_size)
{
    const float* x        = (const float*)d_in[0];
    const int*   edge_src = (const int*)  d_in[1];
    const int*   edge_dst = (const int*)  d_in[2];
    const float* edge_w   = (const float*)d_in[3];
    const float* W1       = (const float*)d_in[4];
    const float* b1       = (const float*)d_in[5];
    const float* W2       = (const float*)d_in[6];
    const float* b2       = (const float*)d_in[7];
    float* out = (float*)d_out;

    int nNodes = in_sizes[0] / N_FEAT;
    int nEdges = in_sizes[1];
    int n_f4 = nNodes * N_HID / 4;

    // Fork: zero on s2 concurrent with gemm1; join before aggregation.
    cudaStream_t s2 = 0;
    cudaEvent_t evF = 0, evJ = 0;
    bool forked =
        (cudaStreamCreateWithFlags(&s2, cudaStreamNonBlocking) == cudaSuccess) &&
        (cudaEventCreateWithFlags(&evF, cudaEventDisableTiming) == cudaSuccess) &&
        (cudaEventCreateWithFlags(&evJ, cudaEventDisableTiming) == cudaSuccess);
    if (!forked) s2 = 0;

    if (forked) {
        cudaEventRecord(evF, 0);
        cudaStreamWaitEvent(s2, evF, 0);
    }

    zero_kernel<<<(n_f4 + 255) / 256, 256, 0, s2>>>(n_f4);

    gemm1_kernel<<<(nNodes + GROWS - 1) / GROWS, 128>>>(x, W1, nNodes);

    if (forked) {
        cudaEventRecord(evJ, s2);
        cudaStreamWaitEvent(0, evJ, 0);
    }

    int aggThreads = nEdges * 4;
    aggregate1_kernel<<<(aggThreads + 255) / 256, 256>>>(
        edge_src, edge_dst, edge_w, nEdges);

    aggregate2_kernel<<<(aggThreads + 255) / 256, 256>>>(
        edge_src, edge_dst, edge_w, b1, nEdges);

    head_kernel<<<(nNodes + 127) / 128, 128>>>(W2, b2, out, nNodes);
}